// round 13
// baseline (speedup 1.0000x reference)
#include <cuda_runtime.h>
#include <cuda_bf16.h>
#include <cstdint>
#include <math.h>

// ============================================================================
// Controller_29076928594279 — ENAS LSTM controller sampler, one SM, one block.
// Design frozen pending first hardware evidence (13 rounds of GPU timeouts).
//
//  * 256 threads; thread j owns gate-output j. Its 128 weights (w_ih row j and
//    w_hh row j) live in registers as 64 packed f32x2 values. Each LSTM step
//    is 64 fma.rn.f32x2 against the shared [x;h] vector, read with 32 LDS.128
//    broadcast loads (ulonglong2).
//  * Gate nonlinearities applied per-thread across all 8 warps; combined bias
//    (b_ih+b_hh) held in a register.
//  * Weights staged global->smem coalesced in 4 quarter-passes (64 rows at a
//    time); the staging buffer is then REUSED for the transposed attention
//    matrices, keeping dynamic smem at 33.3 KB (< 48 KB default: no
//    cudaFuncSetAttribute, nothing capture-hostile in kernel_launch).
//  * w_attn1/w_attn2 transposed in smem (stride 65, conflict-free col dots).
//  * RNG: JAX threefry2x32, partitionable mode:
//      split(key,n)[i]    = threefry(key,(0,i)) (both words)
//      random_bits(32)[i] = out0 ^ out1 of threefry(key,(0,i))
//      uniform = max(tiny, f*(1-tiny)+tiny),  f = ((bits>>9)|0x3f800000)-1
//      categorical = argmax(logits - log(-log(u))), first-max tiebreak
//  * Output: [arc1(20), arc2(20), log_prob, entropy] = 42 float32.
// ============================================================================

#define NTHREADS 256
#define STG_COLS 66                          // 64 + 2 pad (keeps 8B row align)
#define A1_OFF 0
#define A2_OFF (64 * 65)
#define DYN_FLOATS (2 * 64 * 65)             // 8320 floats = 33280 B
#define DYN_BYTES (DYN_FLOATS * 4)
// staging uses floats [0, 64*66) = 4224 of the same buffer, before attn fill

#define FMA2(d, a, b) asm("fma.rn.f32x2 %0, %1, %2, %0;" : "+l"(d) : "l"(a), "l"(b))

__device__ __forceinline__ void tf2x32(uint32_t k0, uint32_t k1,
                                       uint32_t x0, uint32_t x1,
                                       uint32_t& o0, uint32_t& o1) {
    uint32_t ks2 = k0 ^ k1 ^ 0x1BD11BDAu;
    x0 += k0; x1 += k1;
#define TFR(r) { x0 += x1; x1 = (x1 << (r)) | (x1 >> (32 - (r))); x1 ^= x0; }
    TFR(13) TFR(15) TFR(26) TFR(6)   x0 += k1;  x1 += ks2 + 1u;
    TFR(17) TFR(29) TFR(16) TFR(24)  x0 += ks2; x1 += k0 + 2u;
    TFR(13) TFR(15) TFR(26) TFR(6)   x0 += k0;  x1 += k1 + 3u;
    TFR(17) TFR(29) TFR(16) TFR(24)  x0 += k1;  x1 += ks2 + 4u;
    TFR(13) TFR(15) TFR(26) TFR(6)   x0 += ks2; x1 += k0 + 5u;
#undef TFR
    o0 = x0; o1 = x1;
}

// Warp 0 only (all 32 lanes active). Result valid on lane 0; lp/ent updated
// on lane 0 only.
__device__ __forceinline__ int do_sample(int n, uint32_t kx, uint32_t ky, int lane,
                                         const float* logits_s, float& lp, float& ent) {
    const float NEG_INF = __int_as_float(0xff800000);
    uint32_t o0 = 0u, o1 = 0u;
    if (lane < n) tf2x32(kx, ky, 0u, (uint32_t)lane, o0, o1);
    uint32_t bits = o0 ^ o1;
    float v = NEG_INF;
    if (lane < n) {
        float f = __uint_as_float((bits >> 9) | 0x3f800000u) - 1.0f;   // [0,1)
        const float TINY = 1.1754943508222875e-38f;
        float u = fmaxf(TINY, f * (1.0f - TINY) + TINY);
        float gum = -logf(-logf(u));
        v = logits_s[lane] + gum;
    }
    int bi = lane;
#pragma unroll
    for (int off = 16; off; off >>= 1) {
        float ov = __shfl_down_sync(0xffffffffu, v, off);
        int   oi = __shfl_down_sync(0xffffffffu, bi, off);
        if (ov > v || (ov == v && oi < bi)) { v = ov; bi = oi; }
    }
    if (lane == 0) {
        float mx = NEG_INF;
        for (int i = 0; i < n; i++) mx = fmaxf(mx, logits_s[i]);
        float se = 0.0f;
        for (int i = 0; i < n; i++) se += expf(logits_s[i] - mx);
        float lse = mx + logf(se);
        lp += lse - logits_s[bi];                 // -= logp[index]
        float e = 0.0f;
        for (int i = 0; i < n; i++) { float q = logits_s[i] - lse; e += q * expf(q); }
        ent += -e;                                // -sum(logp * exp(logp))
    }
    return bi;
}

__global__ __launch_bounds__(NTHREADS, 1)
void ctrl_kernel(const float* __restrict__ embed,   const float* __restrict__ w_ih,
                 const float* __restrict__ w_hh,    const float* __restrict__ b_ih,
                 const float* __restrict__ b_hh,    const float* __restrict__ w_soft,
                 const float* __restrict__ b_soft,  const float* __restrict__ b_snl,
                 const float* __restrict__ w_attn1, const float* __restrict__ w_attn2,
                 const float* __restrict__ v_attn,  const int* __restrict__ seedp,
                 float* __restrict__ out) {
    extern __shared__ float dynsm[];
    float* stg = dynsm;             // staging: 64 rows x 66 floats (prologue only)
    float* a1T = dynsm + A1_OFF;    // after staging: a1T[k*65+j] = w_attn1[j][k]
    float* a2T = dynsm + A2_OFF;

    __shared__ __align__(16) float xh_s[128];    // [x(64) ; h(64)]
    __shared__ float c_s[64], gact[256], hw2_s[64];
    __shared__ float anchors_s[7 * 64], aW1_s[7 * 64];
    __shared__ float embed_s[6 * 64], wsoft_s[5 * 64], vattn_s[64];
    __shared__ float bsoft_s[5], bsnl_s[5], logits_s[8];
    __shared__ uint32_t keyflat_s[80];           // 2 samplers * 20 keys * 2 words
    __shared__ int idx_s;
    __shared__ int arc_s[40];

    const int tid = threadIdx.x;

    // ------------------- small one-time fills (static smem only) -------------
    for (int i = tid; i < 384; i += NTHREADS) embed_s[i] = embed[i];
    for (int i = tid; i < 320; i += NTHREADS) wsoft_s[i] = w_soft[i];
    const float bsum_r = b_ih[tid] + b_hh[tid];  // per-thread constant, register
    if (tid < 64) vattn_s[tid] = v_attn[tid];
    if (tid < 5) { bsoft_s[tid] = b_soft[tid]; bsnl_s[tid] = b_snl[tid]; }
    if (tid < 40) {
        // root = (0, (u32)seed); sampler key = split(root,2)[s];
        // per-sample key = split(sampler_key, 20)[i]
        uint32_t r0 = 0u, r1 = (uint32_t)seedp[0];
        int s = tid / 20, i = tid % 20;
        uint32_t s0, s1, q0, q1;
        tf2x32(r0, r1, 0u, (uint32_t)s, s0, s1);
        tf2x32(s0, s1, 0u, (uint32_t)i, q0, q1);
        keyflat_s[tid * 2] = q0; keyflat_s[tid * 2 + 1] = q1;
    }

    // ------------------- weight staging -> registers (4 quarter-passes each) --
    // Pass p stages rows [p*64, (p+1)*64); threads with tid>>6 == p read their
    // own row into registers. Coalesced global reads, 2-way smem read conflict.
    unsigned long long wreg[64];
#pragma unroll 1
    for (int p = 0; p < 4; ++p) {
        for (int i = tid; i < 4096; i += NTHREADS) {
            int r = i >> 6, c = i & 63;
            stg[r * STG_COLS + c] = w_ih[(p * 64 + r) * 64 + c];
        }
        __syncthreads();
        if ((tid >> 6) == p) {
            const unsigned long long* srow =
                reinterpret_cast<const unsigned long long*>(stg + (tid & 63) * STG_COLS);
#pragma unroll
            for (int k = 0; k < 32; ++k) wreg[k] = srow[k];
        }
        __syncthreads();
    }
#pragma unroll 1
    for (int p = 0; p < 4; ++p) {
        for (int i = tid; i < 4096; i += NTHREADS) {
            int r = i >> 6, c = i & 63;
            stg[r * STG_COLS + c] = w_hh[(p * 64 + r) * 64 + c];
        }
        __syncthreads();
        if ((tid >> 6) == p) {
            const unsigned long long* srow =
                reinterpret_cast<const unsigned long long*>(stg + (tid & 63) * STG_COLS);
#pragma unroll
            for (int k = 0; k < 32; ++k) wreg[32 + k] = srow[k];
        }
        __syncthreads();
    }

    // ------------------- attn matrices into (reused) dynamic smem -------------
    for (int i = tid; i < 4096; i += NTHREADS) {
        int j = i >> 6, k = i & 63;
        a1T[k * 65 + j] = w_attn1[i];
        a2T[k * 65 + j] = w_attn2[i];
    }
    // fenced by the __syncthreads at the top of the first lstm_step

    float lp = 0.0f, ent = 0.0f;
    const bool is_g_gate = ((tid >> 6) == 2);    // gate 2 = candidate (tanh)
    const float pre_scale = is_g_gate ? 1.0f : 0.5f;
    const float act_a     = is_g_gate ? 1.0f : 0.5f;
    const float act_b     = is_g_gate ? 0.0f : 0.5f;

    // One LSTM step: reads xh_s, writes new h into xh_s[64:128], c into c_s.
    auto lstm_step = [&]() {
        __syncthreads();   // xh_s (and preceding smem writes) ready
        unsigned long long a0 = 0ull, a1 = 0ull, a2 = 0ull, a3 = 0ull;
        const ulonglong2* xv2 = reinterpret_cast<const ulonglong2*>(xh_s);
#pragma unroll
        for (int k = 0; k < 32; k += 2) {       // 32 LDS.128 broadcast loads
            ulonglong2 w0 = xv2[k];
            ulonglong2 w1 = xv2[k + 1];
            FMA2(a0, wreg[2 * k],     w0.x);
            FMA2(a1, wreg[2 * k + 1], w0.y);
            FMA2(a2, wreg[2 * k + 2], w1.x);
            FMA2(a3, wreg[2 * k + 3], w1.y);
        }
        float2 f0 = *reinterpret_cast<float2*>(&a0);
        float2 f1 = *reinterpret_cast<float2*>(&a1);
        float2 f2 = *reinterpret_cast<float2*>(&a2);
        float2 f3 = *reinterpret_cast<float2*>(&a3);
        float pre = bsum_r +
                    ((f0.x + f0.y) + (f1.x + f1.y)) + ((f2.x + f2.y) + (f3.x + f3.y));
        // per-thread gate nonlinearity (8 warps in parallel):
        // i/f/o -> logistic = 0.5*tanh(0.5*x)+0.5 ; g -> tanh(x)
        gact[tid] = fmaf(act_a, tanhf(pre_scale * pre), act_b);
        __syncthreads();
        if (tid < 64) {
            float c2 = gact[64 + tid] * c_s[tid] + gact[tid] * gact[128 + tid];
            c_s[tid] = c2;
            xh_s[64 + tid] = gact[192 + tid] * tanhf(c2);
        }
        __syncthreads();   // h ready for consumers
    };

    for (int s = 0; s < 2; ++s) {
        const bool use_bias = (s == 0);
        if (tid < 128) anchors_s[tid] = 0.0f;    // warmup anchors are zeros
        if (tid < 64) {
            xh_s[tid] = embed_s[tid];            // inputs = embed[0]
            if (s == 0) { c_s[tid] = 0.0f; xh_s[64 + tid] = 0.0f; }
        }
        int kc = 0;

        // -------- warmup: 2 anchor slots --------
        for (int slot = 0; slot < 2; ++slot) {
            lstm_step();
            if (tid < 64) {
                float d0 = 0.f, d1 = 0.f, d2 = 0.f, d3 = 0.f;
#pragma unroll
                for (int k = 0; k < 64; k += 4) {
                    d0 = fmaf(xh_s[64 + k],     a1T[k * 65 + tid],       d0);
                    d1 = fmaf(xh_s[64 + k + 1], a1T[(k + 1) * 65 + tid], d1);
                    d2 = fmaf(xh_s[64 + k + 2], a1T[(k + 2) * 65 + tid], d2);
                    d3 = fmaf(xh_s[64 + k + 3], a1T[(k + 3) * 65 + tid], d3);
                }
                aW1_s[slot * 64 + tid] = (d0 + d1) + (d2 + d3);
            }
        }

        // -------- layers 2..6 --------
        for (int layer = 2; layer < 7; ++layer) {
            int arcbase = s * 20 + (layer - 2) * 4;

            // two previous-layer index samples (tiny attention)
            for (int t = 0; t < 2; ++t) {
                lstm_step();
                if (tid < 64) {   // hW2[j] = dot(h, w_attn2 row j)
                    float d0 = 0.f, d1 = 0.f, d2 = 0.f, d3 = 0.f;
#pragma unroll
                    for (int k = 0; k < 64; k += 4) {
                        d0 = fmaf(xh_s[64 + k],     a2T[k * 65 + tid],       d0);
                        d1 = fmaf(xh_s[64 + k + 1], a2T[(k + 1) * 65 + tid], d1);
                        d2 = fmaf(xh_s[64 + k + 2], a2T[(k + 2) * 65 + tid], d2);
                        d3 = fmaf(xh_s[64 + k + 3], a2T[(k + 3) * 65 + tid], d3);
                    }
                    hw2_s[tid] = (d0 + d1) + (d2 + d3);
                }
                __syncthreads();
                if (tid < 64) {   // logits[r] = sum_j tanh(aW1[r][j]+hW2[j]) * v[j]
                    int w = tid >> 5, l = tid & 31;
                    for (int r = w; r < layer; r += 2) {
                        float p = tanhf(aW1_s[r * 64 + l] + hw2_s[l]) * vattn_s[l]
                                + tanhf(aW1_s[r * 64 + 32 + l] + hw2_s[32 + l]) * vattn_s[32 + l];
#pragma unroll
                        for (int off = 16; off; off >>= 1)
                            p += __shfl_down_sync(0xffffffffu, p, off);
                        if (l == 0) logits_s[r] = p / 5.0f + 1.1f * tanhf(p);
                    }
                }
                __syncthreads();
                if (tid < 32) {
                    int kk = (s * 20 + kc) * 2;
                    int bi = do_sample(layer, keyflat_s[kk], keyflat_s[kk + 1],
                                       tid, logits_s, lp, ent);
                    if (tid == 0) { idx_s = bi; arc_s[arcbase + t * 2] = bi; }
                }
                kc++;
                __syncthreads();
                if (tid < 64) xh_s[tid] = anchors_s[idx_s * 64 + tid];
            }

            // two op samples
            for (int t = 0; t < 2; ++t) {
                lstm_step();
                if (tid < 64) {
                    int w = tid >> 5, l = tid & 31;
                    for (int o = w; o < 5; o += 2) {
                        float p = xh_s[64 + l] * wsoft_s[o * 64 + l]
                                + xh_s[64 + 32 + l] * wsoft_s[o * 64 + 32 + l];
#pragma unroll
                        for (int off = 16; off; off >>= 1)
                            p += __shfl_down_sync(0xffffffffu, p, off);
                        if (l == 0) {
                            float raw = p + bsoft_s[o];
                            float v = (1.1f / 2.5f) * tanhf(raw / 5.0f);
                            if (use_bias) v += bsnl_s[o];
                            logits_s[o] = v;
                        }
                    }
                }
                __syncthreads();
                if (tid < 32) {
                    int kk = (s * 20 + kc) * 2;
                    int bo = do_sample(5, keyflat_s[kk], keyflat_s[kk + 1],
                                       tid, logits_s, lp, ent);
                    if (tid == 0) { idx_s = bo; arc_s[arcbase + t * 2 + 1] = bo; }
                }
                kc++;
                __syncthreads();
                if (tid < 64) xh_s[tid] = embed_s[(idx_s + 1) * 64 + tid];
            }

            // anchor step
            lstm_step();
            if (tid < 64) {
                float d0 = 0.f, d1 = 0.f, d2 = 0.f, d3 = 0.f;
#pragma unroll
                for (int k = 0; k < 64; k += 4) {
                    d0 = fmaf(xh_s[64 + k],     a1T[k * 65 + tid],       d0);
                    d1 = fmaf(xh_s[64 + k + 1], a1T[(k + 1) * 65 + tid], d1);
                    d2 = fmaf(xh_s[64 + k + 2], a1T[(k + 2) * 65 + tid], d2);
                    d3 = fmaf(xh_s[64 + k + 3], a1T[(k + 3) * 65 + tid], d3);
                }
                aW1_s[layer * 64 + tid] = (d0 + d1) + (d2 + d3);
                anchors_s[layer * 64 + tid] = xh_s[64 + tid];
                xh_s[tid] = embed_s[tid];    // inputs = embed[0]
            }
        }
    }

    __syncthreads();
    if (tid < 40) out[tid] = (float)arc_s[tid];
    if (tid == 0) { out[40] = lp; out[41] = ent; }
}

extern "C" void kernel_launch(void* const* d_in, const int* in_sizes, int n_in,
                              void* d_out, int out_size) {
    (void)in_sizes; (void)n_in; (void)out_size;
    ctrl_kernel<<<1, NTHREADS, DYN_BYTES>>>(
        (const float*)d_in[0],  (const float*)d_in[1],  (const float*)d_in[2],
        (const float*)d_in[3],  (const float*)d_in[4],  (const float*)d_in[5],
        (const float*)d_in[6],  (const float*)d_in[7],  (const float*)d_in[8],
        (const float*)d_in[9],  (const float*)d_in[10], (const int*)d_in[11],
        (float*)d_out);
}

// round 16
// speedup vs baseline: 1.0652x; 1.0652x over previous
#include <cuda_runtime.h>
#include <cuda_bf16.h>
#include <cstdint>
#include <math.h>

// ============================================================================
// Controller_29076928594279 — ENAS LSTM controller sampler, one SM, one block.
// R14..R16: post-mortem of first real bench (100.8us, issue=13.1%, regs=234)
// showed the bottleneck is libdevice software transcendentals + serial lane-0
// softmax, NOT the matvec. Fix: MUFU-based tanh/exp/log, parallel warp
// softmax, divisions -> multiplies. Everything else unchanged from the
// verified (rel_err=0.0) kernel. Resubmitted unchanged pending measurement.
//
//  * RNG: JAX threefry2x32 partitionable (verified bit-exact).
//  * Output: [arc1(20), arc2(20), log_prob, entropy] = 42 float32.
// ============================================================================

#define NTHREADS 256
#define STG_COLS 66                          // 64 + 2 pad (keeps 8B row align)
#define A1_OFF 0
#define A2_OFF (64 * 65)
#define DYN_FLOATS (2 * 64 * 65)             // 8320 floats = 33280 B
#define DYN_BYTES (DYN_FLOATS * 4)

#define FMA2(d, a, b) asm("fma.rn.f32x2 %0, %1, %2, %0;" : "+l"(d) : "l"(a), "l"(b))

// Fast transcendentals (MUFU-based, rel err ~1e-6; tolerance is 1e-3).
__device__ __forceinline__ float ftanh(float x) {
    // 1 - 2/(e^{2x}+1); x->+inf: e=inf -> 1; x->-inf: e=0 -> -1.
    float e = __expf(2.0f * x);
    return 1.0f - __fdividef(2.0f, e + 1.0f);
}

__device__ __forceinline__ void tf2x32(uint32_t k0, uint32_t k1,
                                       uint32_t x0, uint32_t x1,
                                       uint32_t& o0, uint32_t& o1) {
    uint32_t ks2 = k0 ^ k1 ^ 0x1BD11BDAu;
    x0 += k0; x1 += k1;
#define TFR(r) { x0 += x1; x1 = (x1 << (r)) | (x1 >> (32 - (r))); x1 ^= x0; }
    TFR(13) TFR(15) TFR(26) TFR(6)   x0 += k1;  x1 += ks2 + 1u;
    TFR(17) TFR(29) TFR(16) TFR(24)  x0 += ks2; x1 += k0 + 2u;
    TFR(13) TFR(15) TFR(26) TFR(6)   x0 += k0;  x1 += k1 + 3u;
    TFR(17) TFR(29) TFR(16) TFR(24)  x0 += k1;  x1 += ks2 + 4u;
    TFR(13) TFR(15) TFR(26) TFR(6)   x0 += ks2; x1 += k0 + 5u;
#undef TFR
    o0 = x0; o1 = x1;
}

// Warp 0 only (all 32 lanes active). Result valid on lane 0; lp/ent updated
// on lane 0 only. Softmax stats computed with parallel butterfly reductions.
__device__ __forceinline__ int do_sample(int n, uint32_t kx, uint32_t ky, int lane,
                                         const float* logits_s, float& lp, float& ent) {
    const float NEG_INF = __int_as_float(0xff800000);
    uint32_t o0 = 0u, o1 = 0u;
    if (lane < n) tf2x32(kx, ky, 0u, (uint32_t)lane, o0, o1);
    uint32_t bits = o0 ^ o1;
    float lg = (lane < n) ? logits_s[lane] : NEG_INF;
    float v = NEG_INF;
    if (lane < n) {
        float f = __uint_as_float((bits >> 9) | 0x3f800000u) - 1.0f;   // [0,1)
        const float TINY = 1.1754943508222875e-38f;
        float u = fmaxf(TINY, f * (1.0f - TINY) + TINY);
        float gum = -__logf(-__logf(u));
        v = lg + gum;
    }
    // argmax(logits+gumbel), first-max tiebreak
    int bi = lane;
#pragma unroll
    for (int off = 16; off; off >>= 1) {
        float ov = __shfl_down_sync(0xffffffffu, v, off);
        int   oi = __shfl_down_sync(0xffffffffu, bi, off);
        if (ov > v || (ov == v && oi < bi)) { v = ov; bi = oi; }
    }
    // parallel softmax stats (all lanes end with same values)
    float mx = lg;
#pragma unroll
    for (int off = 16; off; off >>= 1) mx = fmaxf(mx, __shfl_xor_sync(0xffffffffu, mx, off));
    float ex = (lane < n) ? __expf(lg - mx) : 0.0f;
    float se = ex;
#pragma unroll
    for (int off = 16; off; off >>= 1) se += __shfl_xor_sync(0xffffffffu, se, off);
    float lse = mx + __logf(se);
    float q  = lg - lse;
    float et = (lane < n) ? q * __expf(q) : 0.0f;
#pragma unroll
    for (int off = 16; off; off >>= 1) et += __shfl_xor_sync(0xffffffffu, et, off);
    if (lane == 0) {
        lp += lse - logits_s[bi];                 // -= logp[index]
        ent += -et;                               // -sum(logp * exp(logp))
    }
    return bi;
}

__global__ __launch_bounds__(NTHREADS, 1)
void ctrl_kernel(const float* __restrict__ embed,   const float* __restrict__ w_ih,
                 const float* __restrict__ w_hh,    const float* __restrict__ b_ih,
                 const float* __restrict__ b_hh,    const float* __restrict__ w_soft,
                 const float* __restrict__ b_soft,  const float* __restrict__ b_snl,
                 const float* __restrict__ w_attn1, const float* __restrict__ w_attn2,
                 const float* __restrict__ v_attn,  const int* __restrict__ seedp,
                 float* __restrict__ out) {
    extern __shared__ float dynsm[];
    float* stg = dynsm;             // staging: 64 rows x 66 floats (prologue only)
    float* a1T = dynsm + A1_OFF;    // after staging: a1T[k*65+j] = w_attn1[j][k]
    float* a2T = dynsm + A2_OFF;

    __shared__ __align__(16) float xh_s[128];    // [x(64) ; h(64)]
    __shared__ float c_s[64], gact[256], hw2_s[64];
    __shared__ float anchors_s[7 * 64], aW1_s[7 * 64];
    __shared__ float embed_s[6 * 64], wsoft_s[5 * 64], vattn_s[64];
    __shared__ float bsoft_s[5], bsnl_s[5], logits_s[8];
    __shared__ uint32_t keyflat_s[80];           // 2 samplers * 20 keys * 2 words
    __shared__ int idx_s;
    __shared__ int arc_s[40];

    const int tid = threadIdx.x;

    // ------------------- small one-time fills (static smem only) -------------
    for (int i = tid; i < 384; i += NTHREADS) embed_s[i] = embed[i];
    for (int i = tid; i < 320; i += NTHREADS) wsoft_s[i] = w_soft[i];
    const float bsum_r = b_ih[tid] + b_hh[tid];  // per-thread constant, register
    if (tid < 64) vattn_s[tid] = v_attn[tid];
    if (tid < 5) { bsoft_s[tid] = b_soft[tid]; bsnl_s[tid] = b_snl[tid]; }
    if (tid < 40) {
        uint32_t r0 = 0u, r1 = (uint32_t)seedp[0];
        int s = tid / 20, i = tid % 20;
        uint32_t s0, s1, q0, q1;
        tf2x32(r0, r1, 0u, (uint32_t)s, s0, s1);
        tf2x32(s0, s1, 0u, (uint32_t)i, q0, q1);
        keyflat_s[tid * 2] = q0; keyflat_s[tid * 2 + 1] = q1;
    }

    // ------------------- weight staging -> registers (4 quarter-passes each) --
    unsigned long long wreg[64];
#pragma unroll 1
    for (int p = 0; p < 4; ++p) {
        for (int i = tid; i < 4096; i += NTHREADS) {
            int r = i >> 6, c = i & 63;
            stg[r * STG_COLS + c] = w_ih[(p * 64 + r) * 64 + c];
        }
        __syncthreads();
        if ((tid >> 6) == p) {
            const unsigned long long* srow =
                reinterpret_cast<const unsigned long long*>(stg + (tid & 63) * STG_COLS);
#pragma unroll
            for (int k = 0; k < 32; ++k) wreg[k] = srow[k];
        }
        __syncthreads();
    }
#pragma unroll 1
    for (int p = 0; p < 4; ++p) {
        for (int i = tid; i < 4096; i += NTHREADS) {
            int r = i >> 6, c = i & 63;
            stg[r * STG_COLS + c] = w_hh[(p * 64 + r) * 64 + c];
        }
        __syncthreads();
        if ((tid >> 6) == p) {
            const unsigned long long* srow =
                reinterpret_cast<const unsigned long long*>(stg + (tid & 63) * STG_COLS);
#pragma unroll
            for (int k = 0; k < 32; ++k) wreg[32 + k] = srow[k];
        }
        __syncthreads();
    }

    // ------------------- attn matrices into (reused) dynamic smem -------------
    for (int i = tid; i < 4096; i += NTHREADS) {
        int j = i >> 6, k = i & 63;
        a1T[k * 65 + j] = w_attn1[i];
        a2T[k * 65 + j] = w_attn2[i];
    }
    // fenced by the __syncthreads at the top of the first lstm_step

    float lp = 0.0f, ent = 0.0f;
    const bool is_g_gate = ((tid >> 6) == 2);    // gate 2 = candidate (tanh)
    const float pre_scale = is_g_gate ? 1.0f : 0.5f;
    const float act_a     = is_g_gate ? 1.0f : 0.5f;
    const float act_b     = is_g_gate ? 0.0f : 0.5f;

    // One LSTM step: reads xh_s, writes new h into xh_s[64:128], c into c_s.
    auto lstm_step = [&]() {
        __syncthreads();   // xh_s (and preceding smem writes) ready
        unsigned long long a0 = 0ull, a1 = 0ull, a2 = 0ull, a3 = 0ull;
        const ulonglong2* xv2 = reinterpret_cast<const ulonglong2*>(xh_s);
#pragma unroll
        for (int k = 0; k < 32; k += 2) {       // 32 LDS.128 broadcast loads
            ulonglong2 w0 = xv2[k];
            ulonglong2 w1 = xv2[k + 1];
            FMA2(a0, wreg[2 * k],     w0.x);
            FMA2(a1, wreg[2 * k + 1], w0.y);
            FMA2(a2, wreg[2 * k + 2], w1.x);
            FMA2(a3, wreg[2 * k + 3], w1.y);
        }
        float2 f0 = *reinterpret_cast<float2*>(&a0);
        float2 f1 = *reinterpret_cast<float2*>(&a1);
        float2 f2 = *reinterpret_cast<float2*>(&a2);
        float2 f3 = *reinterpret_cast<float2*>(&a3);
        float pre = bsum_r +
                    ((f0.x + f0.y) + (f1.x + f1.y)) + ((f2.x + f2.y) + (f3.x + f3.y));
        // i/f/o -> logistic = 0.5*tanh(0.5*x)+0.5 ; g -> tanh(x)  (MUFU-based)
        gact[tid] = fmaf(act_a, ftanh(pre_scale * pre), act_b);
        __syncthreads();
        if (tid < 64) {
            float c2 = gact[64 + tid] * c_s[tid] + gact[tid] * gact[128 + tid];
            c_s[tid] = c2;
            xh_s[64 + tid] = gact[192 + tid] * ftanh(c2);
        }
        __syncthreads();   // h ready for consumers
    };

    for (int s = 0; s < 2; ++s) {
        const bool use_bias = (s == 0);
        if (tid < 128) anchors_s[tid] = 0.0f;    // warmup anchors are zeros
        if (tid < 64) {
            xh_s[tid] = embed_s[tid];            // inputs = embed[0]
            if (s == 0) { c_s[tid] = 0.0f; xh_s[64 + tid] = 0.0f; }
        }
        int kc = 0;

        // -------- warmup: 2 anchor slots --------
        for (int slot = 0; slot < 2; ++slot) {
            lstm_step();
            if (tid < 64) {
                float d0 = 0.f, d1 = 0.f, d2 = 0.f, d3 = 0.f;
#pragma unroll
                for (int k = 0; k < 64; k += 4) {
                    d0 = fmaf(xh_s[64 + k],     a1T[k * 65 + tid],       d0);
                    d1 = fmaf(xh_s[64 + k + 1], a1T[(k + 1) * 65 + tid], d1);
                    d2 = fmaf(xh_s[64 + k + 2], a1T[(k + 2) * 65 + tid], d2);
                    d3 = fmaf(xh_s[64 + k + 3], a1T[(k + 3) * 65 + tid], d3);
                }
                aW1_s[slot * 64 + tid] = (d0 + d1) + (d2 + d3);
            }
        }

        // -------- layers 2..6 --------
        for (int layer = 2; layer < 7; ++layer) {
            int arcbase = s * 20 + (layer - 2) * 4;

            // two previous-layer index samples (tiny attention)
            for (int t = 0; t < 2; ++t) {
                lstm_step();
                if (tid < 64) {   // hW2[j] = dot(h, w_attn2 row j)
                    float d0 = 0.f, d1 = 0.f, d2 = 0.f, d3 = 0.f;
#pragma unroll
                    for (int k = 0; k < 64; k += 4) {
                        d0 = fmaf(xh_s[64 + k],     a2T[k * 65 + tid],       d0);
                        d1 = fmaf(xh_s[64 + k + 1], a2T[(k + 1) * 65 + tid], d1);
                        d2 = fmaf(xh_s[64 + k + 2], a2T[(k + 2) * 65 + tid], d2);
                        d3 = fmaf(xh_s[64 + k + 3], a2T[(k + 3) * 65 + tid], d3);
                    }
                    hw2_s[tid] = (d0 + d1) + (d2 + d3);
                }
                __syncthreads();
                if (tid < 64) {   // logits[r] = sum_j tanh(aW1[r][j]+hW2[j]) * v[j]
                    int w = tid >> 5, l = tid & 31;
                    for (int r = w; r < layer; r += 2) {
                        float p = ftanh(aW1_s[r * 64 + l] + hw2_s[l]) * vattn_s[l]
                                + ftanh(aW1_s[r * 64 + 32 + l] + hw2_s[32 + l]) * vattn_s[32 + l];
#pragma unroll
                        for (int off = 16; off; off >>= 1)
                            p += __shfl_down_sync(0xffffffffu, p, off);
                        if (l == 0) logits_s[r] = p * 0.2f + 1.1f * ftanh(p);
                    }
                }
                __syncthreads();
                if (tid < 32) {
                    int kk = (s * 20 + kc) * 2;
                    int bi = do_sample(layer, keyflat_s[kk], keyflat_s[kk + 1],
                                       tid, logits_s, lp, ent);
                    if (tid == 0) { idx_s = bi; arc_s[arcbase + t * 2] = bi; }
                }
                kc++;
                __syncthreads();
                if (tid < 64) xh_s[tid] = anchors_s[idx_s * 64 + tid];
            }

            // two op samples
            for (int t = 0; t < 2; ++t) {
                lstm_step();
                if (tid < 64) {
                    int w = tid >> 5, l = tid & 31;
                    for (int o = w; o < 5; o += 2) {
                        float p = xh_s[64 + l] * wsoft_s[o * 64 + l]
                                + xh_s[64 + 32 + l] * wsoft_s[o * 64 + 32 + l];
#pragma unroll
                        for (int off = 16; off; off >>= 1)
                            p += __shfl_down_sync(0xffffffffu, p, off);
                        if (l == 0) {
                            float raw = p + bsoft_s[o];
                            float v = 0.44f * ftanh(raw * 0.2f);   // 1.1/2.5 = 0.44
                            if (use_bias) v += bsnl_s[o];
                            logits_s[o] = v;
                        }
                    }
                }
                __syncthreads();
                if (tid < 32) {
                    int kk = (s * 20 + kc) * 2;
                    int bo = do_sample(5, keyflat_s[kk], keyflat_s[kk + 1],
                                       tid, logits_s, lp, ent);
                    if (tid == 0) { idx_s = bo; arc_s[arcbase + t * 2 + 1] = bo; }
                }
                kc++;
                __syncthreads();
                if (tid < 64) xh_s[tid] = embed_s[(idx_s + 1) * 64 + tid];
            }

            // anchor step
            lstm_step();
            if (tid < 64) {
                float d0 = 0.f, d1 = 0.f, d2 = 0.f, d3 = 0.f;
#pragma unroll
                for (int k = 0; k < 64; k += 4) {
                    d0 = fmaf(xh_s[64 + k],     a1T[k * 65 + tid],       d0);
                    d1 = fmaf(xh_s[64 + k + 1], a1T[(k + 1) * 65 + tid], d1);
                    d2 = fmaf(xh_s[64 + k + 2], a1T[(k + 2) * 65 + tid], d2);
                    d3 = fmaf(xh_s[64 + k + 3], a1T[(k + 3) * 65 + tid], d3);
                }
                aW1_s[layer * 64 + tid] = (d0 + d1) + (d2 + d3);
                anchors_s[layer * 64 + tid] = xh_s[64 + tid];
                xh_s[tid] = embed_s[tid];    // inputs = embed[0]
            }
        }
    }

    __syncthreads();
    if (tid < 40) out[tid] = (float)arc_s[tid];
    if (tid == 0) { out[40] = lp; out[41] = ent; }
}

extern "C" void kernel_launch(void* const* d_in, const int* in_sizes, int n_in,
                              void* d_out, int out_size) {
    (void)in_sizes; (void)n_in; (void)out_size;
    ctrl_kernel<<<1, NTHREADS, DYN_BYTES>>>(
        (const float*)d_in[0],  (const float*)d_in[1],  (const float*)d_in[2],
        (const float*)d_in[3],  (const float*)d_in[4],  (const float*)d_in[5],
        (const float*)d_in[6],  (const float*)d_in[7],  (const float*)d_in[8],
        (const float*)d_in[9],  (const float*)d_in[10], (const int*)d_in[11],
        (float*)d_out);
}